// round 13
// baseline (speedup 1.0000x reference)
#include <cuda_runtime.h>
#include <cstdint>
#include <math.h>

#define NUMB   4
#define PRE    1024
#define CAND   4096
#define HBINS  65536
#define MAXN   200000
#define TOPK   2048

// ---------------- device scratch (static, no runtime alloc) ----------------
// All state is self-cleaning across graph replays:
//  - g_hist / g_ccnt: zeroed by k_thresh after reading (start zeroed by BSS).
//  - g_rowflag: zeroed by k_rank before k_mask ORs into it.
//  - g_cand: stale slots ignored via g_ccnt bound in k_rescore.
__device__ unsigned long long g_keyarr[MAXN];
__device__ unsigned           g_hist[NUMB][HBINS];
__device__ unsigned           g_thr[NUMB];
__device__ int                g_ccnt[NUMB];
__device__ unsigned long long g_cand[NUMB][CAND];
__device__ unsigned long long g_prec[NUMB][CAND];
__device__ float              g_regs[NUMB][CAND][8];
__device__ unsigned long long g_sel[NUMB][PRE];
__device__ float              g_boxes[NUMB][PRE][8];
__device__ unsigned           g_mask[NUMB][PRE][32];
__device__ unsigned           g_rowflag[NUMB][32];

// ---------------- K1: APPROX score pass + histogram (prefetch-pipelined) --
__global__ void __launch_bounds__(256) k_score(
        const float* __restrict__ feat,
        const int*   __restrict__ bidx,
        const float* __restrict__ Wc,
        const float* __restrict__ bc,
        const float* __restrict__ Wr,
        const float* __restrict__ br,
        int N) {
    const int warp = threadIdx.x >> 5;
    const int lane = threadIdx.x & 31;
    const int j    = lane & 15;        // lane within point
    const int sub  = lane >> 4;        // which of the 2 points

    float wd[4][4], w8[4][4];
#pragma unroll
    for (int q = 0; q < 4; q++) {
#pragma unroll
        for (int e = 0; e < 4; e++) {
            int f = 4 * (j + 16 * q) + e;
            wd[q][e] = Wc[f * 2 + 1] - Wc[f * 2 + 0];
            w8[q][e] = Wr[f * 9 + 8];
        }
    }
    const float bd  = bc[1] - bc[0];
    const float b8r = br[8];

    const int base0 = blockIdx.x * 256 + warp * 32;

    float4 c0, c1, c2, c3;
    {
        int p = base0 + sub;
        if (p < N) {
            const float4* f4 = (const float4*)(feat + (size_t)p * 256);
            c0 = f4[j]; c1 = f4[j + 16]; c2 = f4[j + 32]; c3 = f4[j + 48];
        } else {
            c0 = c1 = c2 = c3 = make_float4(0.f, 0.f, 0.f, 0.f);
        }
    }

    for (int it = 0; it < 16; it++) {
        float4 n0, n1, n2, n3;
        int pn = base0 + (it + 1) * 2 + sub;
        if (it < 15 && pn < N) {
            const float4* f4n = (const float4*)(feat + (size_t)pn * 256);
            n0 = f4n[j]; n1 = f4n[j + 16]; n2 = f4n[j + 32]; n3 = f4n[j + 48];
        } else {
            n0 = n1 = n2 = n3 = make_float4(0.f, 0.f, 0.f, 0.f);
        }

        float d0 = c0.x * wd[0][0] + c0.y * wd[0][1] + c0.z * wd[0][2] + c0.w * wd[0][3];
        float d1 = c1.x * wd[1][0] + c1.y * wd[1][1] + c1.z * wd[1][2] + c1.w * wd[1][3];
        float d2 = c2.x * wd[2][0] + c2.y * wd[2][1] + c2.z * wd[2][2] + c2.w * wd[2][3];
        float d3 = c3.x * wd[3][0] + c3.y * wd[3][1] + c3.z * wd[3][2] + c3.w * wd[3][3];
        float accd = (d0 + d1) + (d2 + d3);
        float r0 = c0.x * w8[0][0] + c0.y * w8[0][1] + c0.z * w8[0][2] + c0.w * w8[0][3];
        float r1 = c1.x * w8[1][0] + c1.y * w8[1][1] + c1.z * w8[1][2] + c1.w * w8[1][3];
        float r2 = c2.x * w8[2][0] + c2.y * w8[2][1] + c2.z * w8[2][2] + c2.w * w8[2][3];
        float r3 = c3.x * w8[3][0] + c3.y * w8[3][1] + c3.z * w8[3][2] + c3.w * w8[3][3];
        float accr = (r0 + r1) + (r2 + r3);

#pragma unroll
        for (int o = 8; o > 0; o >>= 1) {
            accd += __shfl_xor_sync(0xffffffffu, accd, o);
            accr += __shfl_xor_sync(0xffffffffu, accr, o);
        }
        int p_cur = base0 + it * 2 + sub;
        if (j == 0 && p_cur < N) {
            float s = 1.0f / ((1.0f + expf(-(accd + bd))) * (1.0f + expf(-(accr + b8r))));
            unsigned sb = __float_as_uint(s);
            g_keyarr[p_cur] = ((unsigned long long)sb << 32) | (unsigned)(~(unsigned)p_cur);
            atomicAdd(&g_hist[bidx[p_cur]][sb >> 16], 1u);
        }
        c0 = n0; c1 = n1; c2 = n2; c3 = n3;
    }
}

// ---------------- K2: fused threshold + hist/ccnt re-zero -----------------
__global__ void __launch_bounds__(1024) k_thresh() {
    const int b = blockIdx.x;
    const int t = threadIdx.x;
    __shared__ unsigned tsum[1024];

    // per-thread: 64 contiguous bins via 16 uint4 (kept in registers)
    uint4* h4 = (uint4*)&g_hist[b][0];
    uint4 v4[16];
    unsigned mysum = 0;
#pragma unroll
    for (int i = 0; i < 16; i++) {
        v4[i] = h4[t * 16 + i];
        mysum += v4[i].x + v4[i].y + v4[i].z + v4[i].w;
    }
    // self-clean for next graph replay (each thread rewrites what it read)
#pragma unroll
    for (int i = 0; i < 16; i++) h4[t * 16 + i] = make_uint4(0, 0, 0, 0);
    if (t == 0) g_ccnt[b] = 0;

    tsum[t] = mysum;
    __syncthreads();
    // inclusive suffix scan over thread sums
    for (int off = 1; off < 1024; off <<= 1) {
        unsigned add = (t + off < 1024) ? tsum[t + off] : 0;
        __syncthreads();
        tsum[t] += add;
        __syncthreads();
    }
    unsigned total = tsum[0];
    unsigned S = (t < 1023) ? tsum[t + 1] : 0;
    if (t == 0 && total < TOPK) g_thr[b] = 0u;
    if (total >= TOPK && S < TOPK && S + mysum >= TOPK) {
        unsigned acc = S;
        int bin = -1;
#pragma unroll
        for (int i = 15; i >= 0; i--) {
            unsigned w0 = v4[i].x, w1 = v4[i].y, w2 = v4[i].z, w3 = v4[i].w;
            if (bin < 0) { acc += w3; if (acc >= TOPK) bin = i * 4 + 3; }
            if (bin < 0) { acc += w2; if (acc >= TOPK) bin = i * 4 + 2; }
            if (bin < 0) { acc += w1; if (acc >= TOPK) bin = i * 4 + 1; }
            if (bin < 0) { acc += w0; if (acc >= TOPK) bin = i * 4 + 0; }
        }
        g_thr[b] = ((unsigned)(t * 64 + bin)) << 16;
    }
}

// ---------------- K3: compact (2 pts/thread, warp-aggregated atomics) -----
__global__ void k_compact(const int* __restrict__ bidx, int N) {
    const int base = (blockIdx.x * 256 + threadIdx.x) * 2;
    const unsigned lane = threadIdx.x & 31;
    unsigned long long key0 = 0ull, key1 = 0ull;
    int b0 = -1, b1 = -1;
    bool p0 = false, p1 = false;
    if (base + 1 < N) {
        ulonglong2 kk = *(const ulonglong2*)&g_keyarr[base];
        int2 bb = *(const int2*)&bidx[base];
        key0 = kk.x; key1 = kk.y; b0 = bb.x; b1 = bb.y;
        p0 = ((unsigned)(key0 >> 32) >= g_thr[b0]);
        p1 = ((unsigned)(key1 >> 32) >= g_thr[b1]);
    } else if (base < N) {
        key0 = g_keyarr[base]; b0 = bidx[base];
        p0 = ((unsigned)(key0 >> 32) >= g_thr[b0]);
    }
#pragma unroll
    for (int s = 0; s < 2; s++) {
        bool pr = s ? p1 : p0;
        int bv = s ? b1 : b0;
        unsigned long long kv = s ? key1 : key0;
#pragma unroll
        for (int bb = 0; bb < NUMB; bb++) {
            unsigned m = __ballot_sync(0xffffffffu, pr && (bv == bb));
            if (m) {
                int leader = __ffs(m) - 1;
                int base2 = 0;
                if ((int)lane == leader) base2 = atomicAdd(&g_ccnt[bb], __popc(m));
                base2 = __shfl_sync(0xffffffffu, base2, leader);
                if (pr && (bv == bb)) {
                    int slot = base2 + __popc(m & ((1u << lane) - 1u));
                    if (slot < CAND) g_cand[bb][slot] = kv;
                }
            }
        }
    }
}

// ---------------- K4: PRECISE rescore + reg-head outputs ------------------
// warp per candidate. Score: compensated f32 -> double (exact ordering).
// Reg outputs: plain f32 tree (1e-3 value tolerance).
// Output key: score(32) | (0x3FFFF - idx)(18) | slot(12).
__global__ void __launch_bounds__(128) k_rescore(
        const float* __restrict__ feat,
        const float* __restrict__ Wc,
        const float* __restrict__ bc,
        const float* __restrict__ Wr,
        const float* __restrict__ br,
        int N) {
    __shared__ float swc0[256], swc1[256], sw8[256];
    __shared__ float sWr[256 * 8];
    for (int i = threadIdx.x; i < 256; i += 128) {
        swc0[i] = Wc[2 * i + 0];
        swc1[i] = Wc[2 * i + 1];
        sw8[i]  = Wr[9 * i + 8];
    }
    for (int i = threadIdx.x; i < 256 * 8; i += 128) {
        int f = i >> 3, o = i & 7;
        sWr[i] = Wr[f * 9 + o];
    }
    __syncthreads();

    const int b = blockIdx.y;
    const int warp = threadIdx.x >> 5;
    const int lane = threadIdx.x & 31;
    const int k = blockIdx.x * 4 + warp;

    int cnt = g_ccnt[b];
    if (cnt > CAND) cnt = CAND;
    unsigned long long key = g_cand[b][k];
    unsigned idx = ~(unsigned)(key & 0xffffffffu);
    bool valid = (k < cnt) && (idx < (unsigned)N);

    double d0 = 0.0, d1 = 0.0, d2 = 0.0;
    float ra[8];
#pragma unroll
    for (int o = 0; o < 8; o++) ra[o] = 0.0f;

    if (valid) {
        const float4* f4 = (const float4*)(feat + (size_t)idx * 256);
        float4 a  = f4[lane * 2 + 0];
        float4 c4 = f4[lane * 2 + 1];
        float fv[8] = {a.x, a.y, a.z, a.w, c4.x, c4.y, c4.z, c4.w};
        const float* wp[3] = {&swc0[lane * 8], &swc1[lane * 8], &sw8[lane * 8]};
        double* dp[3] = {&d0, &d1, &d2};
#pragma unroll
        for (int o = 0; o < 3; o++) {
            float s = 0.0f, comp = 0.0f;
#pragma unroll
            for (int c = 0; c < 8; c++) {
                float v = fv[c], w = wp[o][c];
                float p = __fmul_rn(v, w);
                float e = __fmaf_rn(v, w, -p);
                float t = __fadd_rn(s, p);
                float bv = __fadd_rn(t, -s);
                float c1 = __fadd_rn(s, -__fadd_rn(t, -bv));
                float c2 = __fadd_rn(p, -bv);
                comp = __fadd_rn(comp, __fadd_rn(c1, c2));
                comp = __fadd_rn(comp, e);
                s = t;
            }
            *dp[o] = (double)s + (double)comp;
        }
        // reg head: 8 outputs, plain f32
        const float* wr = &sWr[lane * 8 * 8];
#pragma unroll
        for (int c = 0; c < 8; c++) {
            float v = fv[c];
#pragma unroll
            for (int o = 0; o < 8; o++)
                ra[o] = __fmaf_rn(v, wr[c * 8 + o], ra[o]);
        }
    }
#pragma unroll
    for (int o = 16; o > 0; o >>= 1) {
        d0 += __shfl_xor_sync(0xffffffffu, d0, o);
        d1 += __shfl_xor_sync(0xffffffffu, d1, o);
        d2 += __shfl_xor_sync(0xffffffffu, d2, o);
    }
#pragma unroll
    for (int j = 0; j < 8; j++)
#pragma unroll
        for (int o = 16; o > 0; o >>= 1)
            ra[j] += __shfl_xor_sync(0xffffffffu, ra[j], o);

    if (lane < 8 && valid) {
        g_regs[b][k][lane] = __fadd_rn(ra[lane], br[lane]);
    }
    if (lane == 0) {
        unsigned long long outk = 0ull;
        if (valid) {
            double l0 = d0 + (double)bc[0];
            double l1 = d1 + (double)bc[1];
            double r8 = d2 + (double)br[8];
            double m  = fmax(l0, l1);
            double e0 = exp(l0 - m);
            double e1 = exp(l1 - m);
            double conf = e1 / (e0 + e1);
            double scr  = 1.0 / (1.0 + exp(-r8));
            float sf = (float)(conf * scr);
            outk = ((unsigned long long)__float_as_uint(sf) << 32) |
                   ((unsigned long long)(0x3FFFFu - idx) << 12) |
                   (unsigned long long)k;
        }
        g_prec[b][k] = outk;
    }
}

// ---------------- K5: monolithic 4096 bitonic sort + box assembly ---------
__global__ void __launch_bounds__(1024) k_rank(const int* __restrict__ coor) {
    const int b = blockIdx.x;
    const int t = threadIdx.x;
    __shared__ unsigned long long s[CAND];

    if (t < 32) g_rowflag[b][t] = 0;        // self-clean before k_mask
#pragma unroll
    for (int rr = 0; rr < 4; rr++) s[t + rr * 1024] = g_prec[b][t + rr * 1024];

    for (unsigned k = 2; k <= CAND; k <<= 1) {
        for (unsigned jj = k >> 1; jj > 0; jj >>= 1) {
            __syncthreads();
#pragma unroll
            for (int rr = 0; rr < 4; rr++) {
                unsigned tt = t + rr * 1024;
                unsigned ixj = tt ^ jj;
                if (ixj > tt) {
                    unsigned long long a = s[tt], bb = s[ixj];
                    bool desc = ((tt & k) == 0);
                    if (desc ? (a < bb) : (a > bb)) { s[tt] = bb; s[ixj] = a; }
                }
            }
        }
    }
    __syncthreads();

    unsigned long long key = s[t];          // t < 1024 = top-1024
    g_sel[b][t] = key;

    float out[8];
    if (key != 0ull) {
        unsigned slot = (unsigned)(key & 0xFFFu);
        unsigned idx  = 0x3FFFFu - (unsigned)((key >> 12) & 0x3FFFFu);
        float4 ra = ((const float4*)g_regs[b][slot])[0];
        float4 rb = ((const float4*)g_regs[b][slot])[1];
        float cx = __fmul_rn((float)coor[(size_t)idx * 2 + 0], 0.8f);
        float cy = __fmul_rn((float)coor[(size_t)idx * 2 + 1], 0.8f);
        out[0] = __fadd_rn(cx, ra.x);
        out[1] = __fadd_rn(cy, ra.y);
        out[2] = ra.z;
        out[3] = expf(fminf(fmaxf(ra.w, -6.0f), 6.0f));
        out[4] = expf(fminf(fmaxf(rb.x, -6.0f), 6.0f));
        out[5] = expf(fminf(fmaxf(rb.y, -6.0f), 6.0f));
        out[6] = atan2f(rb.z, rb.w);
        out[7] = __uint_as_float((unsigned)(key >> 32));
    } else {
#pragma unroll
        for (int j2 = 0; j2 < 8; j2++) out[j2] = 0.0f;
    }
#pragma unroll
    for (int j2 = 0; j2 < 8; j2++) g_boxes[b][t][j2] = out[j2];
}

// ---------------- K6: IoU suppression bitmask (parallel) ------------------
__global__ void k_mask() {
    const int b = blockIdx.y;
    const int j = threadIdx.x;
    __shared__ float sx1[PRE], sx2[PRE], sy1[PRE], sy2[PRE], sa[PRE];

    float x = g_boxes[b][j][0], y = g_boxes[b][j][1];
    float l = g_boxes[b][j][3], w = g_boxes[b][j][4];
    bool jv = (g_sel[b][j] != 0ull);
    if (jv) {
        float lh = __fmul_rn(l, 0.5f);
        float wh = __fmul_rn(w, 0.5f);
        sx1[j] = __fadd_rn(x, -lh); sx2[j] = __fadd_rn(x, lh);
        sy1[j] = __fadd_rn(y, -wh); sy2[j] = __fadd_rn(y, wh);
        sa[j]  = __fmul_rn(l, w);
    } else {
        sx1[j] = 1e30f; sx2[j] = -1e30f;
        sy1[j] = 1e30f; sy2[j] = -1e30f;
        sa[j]  = 0.0f;
    }
    __syncthreads();

    const int i0 = blockIdx.x * 32;
    const float X1 = sx1[j], X2 = sx2[j], Y1 = sy1[j], Y2 = sy2[j], A = sa[j];
    for (int ii = 0; ii < 32; ii++) {
        int i = i0 + ii;
        float ix = fmaxf(__fadd_rn(fminf(sx2[i], X2), -fmaxf(sx1[i], X1)), 0.0f);
        float iy = fmaxf(__fadd_rn(fminf(sy2[i], Y2), -fmaxf(sy1[i], Y1)), 0.0f);
        float inter = __fmul_rn(ix, iy);
        float uni = __fadd_rn(__fadd_rn(sa[i], A), -inter);
        float iou = __fdiv_rn(inter, fmaxf(uni, 1e-6f));
        bool s = (j > i) && (iou > 0.1f);
        unsigned bal = __ballot_sync(0xffffffffu, s);
        if ((j & 31) == 0) {
            g_mask[b][i][j >> 5] = bal;
            if (bal) atomicOr(&g_rowflag[b][i >> 5], 1u << (i & 31));
        }
    }
}

// ---------------- K7: serial greedy scan (sparse rows only) + outputs -----
__global__ void k_scan_out(float* __restrict__ dout, int out_size) {
    const int b = blockIdx.x;
    const int t = threadIdx.x;
    __shared__ unsigned srem[32];

    if (t < 32) {
        unsigned rem = 0;
        unsigned flags = g_rowflag[b][t];
        for (int w = 0; w < 32; w++) {
            unsigned fw = __shfl_sync(0xffffffffu, flags, w);
            while (fw) {
                int bp = __ffs(fw) - 1;
                fw &= fw - 1;
                int i = w * 32 + bp;
                unsigned owner = __shfl_sync(0xffffffffu, rem, i >> 5);
                if (!((owner >> (i & 31)) & 1u)) {
                    rem |= g_mask[b][i][t];
                }
            }
        }
        srem[t] = rem;
    }
    __syncthreads();

    bool jv = (g_sel[b][t] != 0ull);
    bool keep = jv && !((srem[t >> 5] >> (t & 31)) & 1u);
    float kf = keep ? 1.0f : 0.0f;

    int obase = (b * PRE + t) * 8;
#pragma unroll
    for (int c = 0; c < 8; c++) {
        if (obase + c < out_size) dout[obase + c] = g_boxes[b][t][c] * kf;
    }
    int lbpos = NUMB * PRE * 8 + b * PRE + t;
    if (lbpos < out_size) dout[lbpos] = 0.0f;
    int kppos = NUMB * PRE * 9 + b * PRE + t;
    if (kppos < out_size) dout[kppos] = kf;
}

// ---------------- launcher ----------------
extern "C" void kernel_launch(void* const* d_in, const int* in_sizes, int n_in,
                              void* d_out, int out_size) {
    const float* feat  = (const float*)d_in[0];
    const int*   bidx  = (const int*)d_in[1];
    const int*   coor  = (const int*)d_in[2];
    const float* Wc    = (const float*)d_in[3];
    const float* bc    = (const float*)d_in[4];
    const float* Wr    = (const float*)d_in[5];
    const float* br    = (const float*)d_in[6];
    float* out = (float*)d_out;

    const int N = in_sizes[1];

    k_score<<<(N + 255) / 256, 256>>>(feat, bidx, Wc, bc, Wr, br, N);
    k_thresh<<<NUMB, 1024>>>();
    k_compact<<<(N + 511) / 512, 256>>>(bidx, N);
    k_rescore<<<dim3(CAND / 4, NUMB), 128>>>(feat, Wc, bc, Wr, br, N);
    k_rank<<<NUMB, 1024>>>(coor);
    k_mask<<<dim3(PRE / 32, NUMB), 1024>>>();
    k_scan_out<<<NUMB, 1024>>>(out, out_size);
}

// round 14
// speedup vs baseline: 1.1904x; 1.1904x over previous
#include <cuda_runtime.h>
#include <cstdint>
#include <math.h>

#define NUMB   4
#define PRE    1024
#define CAND   4096
#define HBINS  65536
#define MAXN   200000
#define TOPK   2048

// ---------------- device scratch (static, no runtime alloc) ----------------
// Self-cleaning across graph replays:
//  - g_hist / g_ccnt: zeroed by k_thresh after reading (BSS-zeroed at start).
//  - g_rowflag: zeroed by k_rank_m2f before k_mask ORs into it.
//  - g_cand: stale slots ignored via g_ccnt bound in k_rescore.
__device__ unsigned long long g_keyarr[MAXN];
__device__ unsigned           g_hist[NUMB][HBINS];
__device__ unsigned           g_thr[NUMB];
__device__ int                g_ccnt[NUMB];
__device__ unsigned long long g_cand[NUMB][CAND];
__device__ unsigned long long g_prec[NUMB][CAND];
__device__ float              g_regs[NUMB][CAND][8];
__device__ unsigned long long g_tmp[NUMB][2048];
__device__ unsigned long long g_sel[NUMB][PRE];
__device__ float              g_boxes[NUMB][PRE][8];
__device__ unsigned           g_mask[NUMB][PRE][32];
__device__ unsigned           g_rowflag[NUMB][32];

// fast double exp: ~3e-13 rel error, ~13 DP ops (vs libdevice ~40+ and DDIV)
__device__ __forceinline__ double fast_exp_d(double x) {
    double y = x * 1.4426950408889634;          // x / ln2
    int ni = __double2int_rn(y);
    double f = y - (double)ni;                   // [-0.5, 0.5]
    double g = f * 0.6931471805599453;           // [-0.347, 0.347]
    double p = 1.0 / 3628800.0;
    p = p * g + 1.0 / 362880.0;
    p = p * g + 1.0 / 40320.0;
    p = p * g + 1.0 / 5040.0;
    p = p * g + 1.0 / 720.0;
    p = p * g + 1.0 / 120.0;
    p = p * g + 1.0 / 24.0;
    p = p * g + 1.0 / 6.0;
    p = p * g + 0.5;
    p = p * g + 1.0;
    p = p * g + 1.0;
    long long bits = __double_as_longlong(p) + ((long long)ni << 52);
    return __longlong_as_double(bits);
}

// ---------------- K1: APPROX score pass + histogram (prefetch-pipelined) --
__global__ void __launch_bounds__(256) k_score(
        const float* __restrict__ feat,
        const int*   __restrict__ bidx,
        const float* __restrict__ Wc,
        const float* __restrict__ bc,
        const float* __restrict__ Wr,
        const float* __restrict__ br,
        int N) {
    const int warp = threadIdx.x >> 5;
    const int lane = threadIdx.x & 31;
    const int j    = lane & 15;
    const int sub  = lane >> 4;

    float wd[4][4], w8[4][4];
#pragma unroll
    for (int q = 0; q < 4; q++) {
#pragma unroll
        for (int e = 0; e < 4; e++) {
            int f = 4 * (j + 16 * q) + e;
            wd[q][e] = Wc[f * 2 + 1] - Wc[f * 2 + 0];
            w8[q][e] = Wr[f * 9 + 8];
        }
    }
    const float bd  = bc[1] - bc[0];
    const float b8r = br[8];

    const int base0 = blockIdx.x * 256 + warp * 32;

    float4 c0, c1, c2, c3;
    {
        int p = base0 + sub;
        if (p < N) {
            const float4* f4 = (const float4*)(feat + (size_t)p * 256);
            c0 = f4[j]; c1 = f4[j + 16]; c2 = f4[j + 32]; c3 = f4[j + 48];
        } else {
            c0 = c1 = c2 = c3 = make_float4(0.f, 0.f, 0.f, 0.f);
        }
    }

    for (int it = 0; it < 16; it++) {
        float4 n0, n1, n2, n3;
        int pn = base0 + (it + 1) * 2 + sub;
        if (it < 15 && pn < N) {
            const float4* f4n = (const float4*)(feat + (size_t)pn * 256);
            n0 = f4n[j]; n1 = f4n[j + 16]; n2 = f4n[j + 32]; n3 = f4n[j + 48];
        } else {
            n0 = n1 = n2 = n3 = make_float4(0.f, 0.f, 0.f, 0.f);
        }

        float d0 = c0.x * wd[0][0] + c0.y * wd[0][1] + c0.z * wd[0][2] + c0.w * wd[0][3];
        float d1 = c1.x * wd[1][0] + c1.y * wd[1][1] + c1.z * wd[1][2] + c1.w * wd[1][3];
        float d2 = c2.x * wd[2][0] + c2.y * wd[2][1] + c2.z * wd[2][2] + c2.w * wd[2][3];
        float d3 = c3.x * wd[3][0] + c3.y * wd[3][1] + c3.z * wd[3][2] + c3.w * wd[3][3];
        float accd = (d0 + d1) + (d2 + d3);
        float r0 = c0.x * w8[0][0] + c0.y * w8[0][1] + c0.z * w8[0][2] + c0.w * w8[0][3];
        float r1 = c1.x * w8[1][0] + c1.y * w8[1][1] + c1.z * w8[1][2] + c1.w * w8[1][3];
        float r2 = c2.x * w8[2][0] + c2.y * w8[2][1] + c2.z * w8[2][2] + c2.w * w8[2][3];
        float r3 = c3.x * w8[3][0] + c3.y * w8[3][1] + c3.z * w8[3][2] + c3.w * w8[3][3];
        float accr = (r0 + r1) + (r2 + r3);

#pragma unroll
        for (int o = 8; o > 0; o >>= 1) {
            accd += __shfl_xor_sync(0xffffffffu, accd, o);
            accr += __shfl_xor_sync(0xffffffffu, accr, o);
        }
        int p_cur = base0 + it * 2 + sub;
        if (j == 0 && p_cur < N) {
            float s = 1.0f / ((1.0f + expf(-(accd + bd))) * (1.0f + expf(-(accr + b8r))));
            unsigned sb = __float_as_uint(s);
            g_keyarr[p_cur] = ((unsigned long long)sb << 32) | (unsigned)(~(unsigned)p_cur);
            atomicAdd(&g_hist[bidx[p_cur]][sb >> 16], 1u);
        }
        c0 = n0; c1 = n1; c2 = n2; c3 = n3;
    }
}

// ---------------- K2: fused threshold + hist/ccnt re-zero -----------------
__global__ void __launch_bounds__(1024) k_thresh() {
    const int b = blockIdx.x;
    const int t = threadIdx.x;
    __shared__ unsigned tsum[1024];

    uint4* h4 = (uint4*)&g_hist[b][0];
    uint4 v4[16];
    unsigned mysum = 0;
#pragma unroll
    for (int i = 0; i < 16; i++) {
        v4[i] = h4[t * 16 + i];
        mysum += v4[i].x + v4[i].y + v4[i].z + v4[i].w;
    }
#pragma unroll
    for (int i = 0; i < 16; i++) h4[t * 16 + i] = make_uint4(0, 0, 0, 0);
    if (t == 0) g_ccnt[b] = 0;

    tsum[t] = mysum;
    __syncthreads();
    for (int off = 1; off < 1024; off <<= 1) {
        unsigned add = (t + off < 1024) ? tsum[t + off] : 0;
        __syncthreads();
        tsum[t] += add;
        __syncthreads();
    }
    unsigned total = tsum[0];
    unsigned S = (t < 1023) ? tsum[t + 1] : 0;
    if (t == 0 && total < TOPK) g_thr[b] = 0u;
    if (total >= TOPK && S < TOPK && S + mysum >= TOPK) {
        unsigned acc = S;
        int bin = -1;
#pragma unroll
        for (int i = 15; i >= 0; i--) {
            unsigned w0 = v4[i].x, w1 = v4[i].y, w2 = v4[i].z, w3 = v4[i].w;
            if (bin < 0) { acc += w3; if (acc >= TOPK) bin = i * 4 + 3; }
            if (bin < 0) { acc += w2; if (acc >= TOPK) bin = i * 4 + 2; }
            if (bin < 0) { acc += w1; if (acc >= TOPK) bin = i * 4 + 1; }
            if (bin < 0) { acc += w0; if (acc >= TOPK) bin = i * 4 + 0; }
        }
        g_thr[b] = ((unsigned)(t * 64 + bin)) << 16;
    }
}

// ---------------- K3: compact (2 pts/thread, warp-aggregated atomics) -----
__global__ void k_compact(const int* __restrict__ bidx, int N) {
    const int base = (blockIdx.x * 256 + threadIdx.x) * 2;
    const unsigned lane = threadIdx.x & 31;
    unsigned long long key0 = 0ull, key1 = 0ull;
    int b0 = -1, b1 = -1;
    bool p0 = false, p1 = false;
    if (base + 1 < N) {
        ulonglong2 kk = *(const ulonglong2*)&g_keyarr[base];
        int2 bb = *(const int2*)&bidx[base];
        key0 = kk.x; key1 = kk.y; b0 = bb.x; b1 = bb.y;
        p0 = ((unsigned)(key0 >> 32) >= g_thr[b0]);
        p1 = ((unsigned)(key1 >> 32) >= g_thr[b1]);
    } else if (base < N) {
        key0 = g_keyarr[base]; b0 = bidx[base];
        p0 = ((unsigned)(key0 >> 32) >= g_thr[b0]);
    }
#pragma unroll
    for (int s = 0; s < 2; s++) {
        bool pr = s ? p1 : p0;
        int bv = s ? b1 : b0;
        unsigned long long kv = s ? key1 : key0;
#pragma unroll
        for (int bb = 0; bb < NUMB; bb++) {
            unsigned m = __ballot_sync(0xffffffffu, pr && (bv == bb));
            if (m) {
                int leader = __ffs(m) - 1;
                int base2 = 0;
                if ((int)lane == leader) base2 = atomicAdd(&g_ccnt[bb], __popc(m));
                base2 = __shfl_sync(0xffffffffu, base2, leader);
                if (pr && (bv == bb)) {
                    int slot = base2 + __popc(m & ((1u << lane) - 1u));
                    if (slot < CAND) g_cand[bb][slot] = kv;
                }
            }
        }
    }
}

// ---------------- K4: PRECISE rescore + reg-head (looped, cheap fp64) -----
// grid (32, NUMB) x 256 threads; each warp handles 16 candidates.
// Output key: score(32) | (0x3FFFF - idx)(18) | slot(12).
__global__ void __launch_bounds__(256) k_rescore(
        const float* __restrict__ feat,
        const float* __restrict__ Wc,
        const float* __restrict__ bc,
        const float* __restrict__ Wr,
        const float* __restrict__ br,
        int N) {
    __shared__ float swc0[256], swc1[256], sw8[256];
    __shared__ float sWr[256 * 8];
    for (int i = threadIdx.x; i < 256; i += 256) {
        swc0[i] = Wc[2 * i + 0];
        swc1[i] = Wc[2 * i + 1];
        sw8[i]  = Wr[9 * i + 8];
    }
    for (int i = threadIdx.x; i < 256 * 8; i += 256) {
        int f = i >> 3, o = i & 7;
        sWr[i] = Wr[f * 9 + o];
    }
    __syncthreads();

    const int b = blockIdx.y;
    const int warp = threadIdx.x >> 5;
    const int lane = threadIdx.x & 31;
    const int wg = blockIdx.x * 8 + warp;       // 0..255

    int cnt = g_ccnt[b];
    if (cnt > CAND) cnt = CAND;
    const double bc0 = (double)bc[0], bc1 = (double)bc[1], br8 = (double)br[8];

    // pre-gather this warp's 16 keys (lane l holds key for iteration l)
    unsigned long long mykey = 0ull;
    if (lane < 16) {
        int kk = wg + 256 * lane;
        if (kk < cnt) mykey = g_cand[b][kk];
    }

#pragma unroll 1
    for (int itk = 0; itk < 16; itk++) {
        const int k = wg + 256 * itk;
        unsigned long long key = __shfl_sync(0xffffffffu, mykey, itk);
        unsigned idx = ~(unsigned)(key & 0xffffffffu);
        bool valid = (k < cnt) && (idx < (unsigned)N);

        if (!valid) {
            if (lane == 0) g_prec[b][k] = 0ull;
            continue;
        }

        const float4* f4 = (const float4*)(feat + (size_t)idx * 256);
        float4 a  = f4[lane * 2 + 0];
        float4 c4 = f4[lane * 2 + 1];
        float fv[8] = {a.x, a.y, a.z, a.w, c4.x, c4.y, c4.z, c4.w};

        // compensated dots for the 3 score features
        float s0 = 0.f, comp0 = 0.f, s1 = 0.f, comp1 = 0.f, s2 = 0.f, comp2 = 0.f;
#pragma unroll
        for (int c = 0; c < 8; c++) {
            float v = fv[c];
            {
                float w = swc0[lane * 8 + c];
                float p = __fmul_rn(v, w);
                float e = __fmaf_rn(v, w, -p);
                float t = __fadd_rn(s0, p);
                float bv = __fadd_rn(t, -s0);
                comp0 = __fadd_rn(comp0, __fadd_rn(__fadd_rn(s0, -__fadd_rn(t, -bv)),
                                                   __fadd_rn(p, -bv)));
                comp0 = __fadd_rn(comp0, e);
                s0 = t;
            }
            {
                float w = swc1[lane * 8 + c];
                float p = __fmul_rn(v, w);
                float e = __fmaf_rn(v, w, -p);
                float t = __fadd_rn(s1, p);
                float bv = __fadd_rn(t, -s1);
                comp1 = __fadd_rn(comp1, __fadd_rn(__fadd_rn(s1, -__fadd_rn(t, -bv)),
                                                   __fadd_rn(p, -bv)));
                comp1 = __fadd_rn(comp1, e);
                s1 = t;
            }
            {
                float w = sw8[lane * 8 + c];
                float p = __fmul_rn(v, w);
                float e = __fmaf_rn(v, w, -p);
                float t = __fadd_rn(s2, p);
                float bv = __fadd_rn(t, -s2);
                comp2 = __fadd_rn(comp2, __fadd_rn(__fadd_rn(s2, -__fadd_rn(t, -bv)),
                                                   __fadd_rn(p, -bv)));
                comp2 = __fadd_rn(comp2, e);
                s2 = t;
            }
        }
        // per-lane logit difference (l1-l0 partial) and r8 partial, in double
        double dd = ((double)s1 + (double)comp1) - ((double)s0 + (double)comp0);
        double dr = (double)s2 + (double)comp2;

        // reg head: 8 outputs, plain f32
        float ra[8];
#pragma unroll
        for (int o = 0; o < 8; o++) ra[o] = 0.0f;
        const float* wr = &sWr[lane * 64];
#pragma unroll
        for (int c = 0; c < 8; c++) {
            float v = fv[c];
#pragma unroll
            for (int o = 0; o < 8; o++)
                ra[o] = __fmaf_rn(v, wr[c * 8 + o], ra[o]);
        }

#pragma unroll
        for (int o = 16; o > 0; o >>= 1) {
            dd += __shfl_xor_sync(0xffffffffu, dd, o);
            dr += __shfl_xor_sync(0xffffffffu, dr, o);
        }
#pragma unroll
        for (int j2 = 0; j2 < 8; j2++)
#pragma unroll
            for (int o = 16; o > 0; o >>= 1)
                ra[j2] += __shfl_xor_sync(0xffffffffu, ra[j2], o);

        if (lane < 8) g_regs[b][k][lane] = __fadd_rn(ra[lane], br[lane]);
        if (lane == 0) {
            double da = dd + (bc1 - bc0);         // l1 - l0
            double r8 = dr + br8;
            double ea = fast_exp_d(-da);
            double eb = fast_exp_d(-r8);
            double w  = (1.0 + ea) * (1.0 + eb);  // score = 1/w
            double r  = (double)(1.0f / (float)w);
            r = r * (2.0 - w * r);
            r = r * (2.0 - w * r);
            float sf = (float)r;
            unsigned long long outk =
                ((unsigned long long)__float_as_uint(sf) << 32) |
                ((unsigned long long)(0x3FFFFu - idx) << 12) |
                (unsigned long long)k;
            g_prec[b][k] = outk;
        }
    }
}

// ---------------- K5a: sort each 1024-chunk descending --------------------
__global__ void k_rank_leaf() {
    const int b = blockIdx.y;
    const int c = blockIdx.x;
    const int t = threadIdx.x;
    __shared__ unsigned long long s[1024];
    s[t] = g_prec[b][c * 1024 + t];

    for (unsigned k = 2; k <= 1024; k <<= 1) {
        for (unsigned jj = k >> 1; jj > 0; jj >>= 1) {
            __syncthreads();
            unsigned ixj = t ^ jj;
            if (ixj > (unsigned)t) {
                unsigned long long a = s[t], bb = s[ixj];
                bool desc = ((t & k) == 0);
                if (desc ? (a < bb) : (a > bb)) { s[t] = bb; s[ixj] = a; }
            }
        }
    }
    __syncthreads();
    g_prec[b][c * 1024 + t] = s[t];
}

// ---------------- K5b: merge chunk pairs -> top 1024 each -----------------
__global__ void k_rank_m1() {
    const int b = blockIdx.y;
    const int c = blockIdx.x;
    const int t = threadIdx.x;
    __shared__ unsigned long long s[2048];
    s[t]        = g_prec[b][(2 * c) * 1024 + t];
    s[2047 - t] = g_prec[b][(2 * c + 1) * 1024 + t];
    for (unsigned jj = 1024; jj > 0; jj >>= 1) {
        __syncthreads();
#pragma unroll
        for (int rr = 0; rr < 2; rr++) {
            unsigned tt = t + rr * 1024;
            unsigned ixj = tt ^ jj;
            if (ixj > tt) {
                unsigned long long a = s[tt], bb = s[ixj];
                if (a < bb) { s[tt] = bb; s[ixj] = a; }
            }
        }
    }
    __syncthreads();
    g_tmp[b][c * 1024 + t] = s[t];
}

// ---------------- K5c: final merge + box assembly + rowflag clean ---------
__global__ void k_rank_m2f(const int* __restrict__ coor) {
    const int b = blockIdx.x;
    const int t = threadIdx.x;
    __shared__ unsigned long long s[2048];
    if (t < 32) g_rowflag[b][t] = 0;        // self-clean before k_mask
    s[t]        = g_tmp[b][t];
    s[2047 - t] = g_tmp[b][1024 + t];
    for (unsigned jj = 1024; jj > 0; jj >>= 1) {
        __syncthreads();
#pragma unroll
        for (int rr = 0; rr < 2; rr++) {
            unsigned tt = t + rr * 1024;
            unsigned ixj = tt ^ jj;
            if (ixj > tt) {
                unsigned long long a = s[tt], bb = s[ixj];
                if (a < bb) { s[tt] = bb; s[ixj] = a; }
            }
        }
    }
    __syncthreads();
    unsigned long long key = s[t];
    g_sel[b][t] = key;

    float out[8];
    if (key != 0ull) {
        unsigned slot = (unsigned)(key & 0xFFFu);
        unsigned idx  = 0x3FFFFu - (unsigned)((key >> 12) & 0x3FFFFu);
        float4 ra = ((const float4*)g_regs[b][slot])[0];
        float4 rb = ((const float4*)g_regs[b][slot])[1];
        float cx = __fmul_rn((float)coor[(size_t)idx * 2 + 0], 0.8f);
        float cy = __fmul_rn((float)coor[(size_t)idx * 2 + 1], 0.8f);
        out[0] = __fadd_rn(cx, ra.x);
        out[1] = __fadd_rn(cy, ra.y);
        out[2] = ra.z;
        out[3] = expf(fminf(fmaxf(ra.w, -6.0f), 6.0f));
        out[4] = expf(fminf(fmaxf(rb.x, -6.0f), 6.0f));
        out[5] = expf(fminf(fmaxf(rb.y, -6.0f), 6.0f));
        out[6] = atan2f(rb.z, rb.w);
        out[7] = __uint_as_float((unsigned)(key >> 32));
    } else {
#pragma unroll
        for (int j2 = 0; j2 < 8; j2++) out[j2] = 0.0f;
    }
#pragma unroll
    for (int j2 = 0; j2 < 8; j2++) g_boxes[b][t][j2] = out[j2];
}

// ---------------- K6: IoU suppression bitmask (parallel) ------------------
__global__ void k_mask() {
    const int b = blockIdx.y;
    const int j = threadIdx.x;
    __shared__ float sx1[PRE], sx2[PRE], sy1[PRE], sy2[PRE], sa[PRE];

    float x = g_boxes[b][j][0], y = g_boxes[b][j][1];
    float l = g_boxes[b][j][3], w = g_boxes[b][j][4];
    bool jv = (g_sel[b][j] != 0ull);
    if (jv) {
        float lh = __fmul_rn(l, 0.5f);
        float wh = __fmul_rn(w, 0.5f);
        sx1[j] = __fadd_rn(x, -lh); sx2[j] = __fadd_rn(x, lh);
        sy1[j] = __fadd_rn(y, -wh); sy2[j] = __fadd_rn(y, wh);
        sa[j]  = __fmul_rn(l, w);
    } else {
        sx1[j] = 1e30f; sx2[j] = -1e30f;
        sy1[j] = 1e30f; sy2[j] = -1e30f;
        sa[j]  = 0.0f;
    }
    __syncthreads();

    const int i0 = blockIdx.x * 32;
    const float X1 = sx1[j], X2 = sx2[j], Y1 = sy1[j], Y2 = sy2[j], A = sa[j];
    for (int ii = 0; ii < 32; ii++) {
        int i = i0 + ii;
        float ix = fmaxf(__fadd_rn(fminf(sx2[i], X2), -fmaxf(sx1[i], X1)), 0.0f);
        float iy = fmaxf(__fadd_rn(fminf(sy2[i], Y2), -fmaxf(sy1[i], Y1)), 0.0f);
        float inter = __fmul_rn(ix, iy);
        float uni = __fadd_rn(__fadd_rn(sa[i], A), -inter);
        float iou = __fdiv_rn(inter, fmaxf(uni, 1e-6f));
        bool s = (j > i) && (iou > 0.1f);
        unsigned bal = __ballot_sync(0xffffffffu, s);
        if ((j & 31) == 0) {
            g_mask[b][i][j >> 5] = bal;
            if (bal) atomicOr(&g_rowflag[b][i >> 5], 1u << (i & 31));
        }
    }
}

// ---------------- K7: serial greedy scan (sparse rows only) + outputs -----
__global__ void k_scan_out(float* __restrict__ dout, int out_size) {
    const int b = blockIdx.x;
    const int t = threadIdx.x;
    __shared__ unsigned srem[32];

    if (t < 32) {
        unsigned rem = 0;
        unsigned flags = g_rowflag[b][t];
        for (int w = 0; w < 32; w++) {
            unsigned fw = __shfl_sync(0xffffffffu, flags, w);
            while (fw) {
                int bp = __ffs(fw) - 1;
                fw &= fw - 1;
                int i = w * 32 + bp;
                unsigned owner = __shfl_sync(0xffffffffu, rem, i >> 5);
                if (!((owner >> (i & 31)) & 1u)) {
                    rem |= g_mask[b][i][t];
                }
            }
        }
        srem[t] = rem;
    }
    __syncthreads();

    bool jv = (g_sel[b][t] != 0ull);
    bool keep = jv && !((srem[t >> 5] >> (t & 31)) & 1u);
    float kf = keep ? 1.0f : 0.0f;

    int obase = (b * PRE + t) * 8;
#pragma unroll
    for (int c = 0; c < 8; c++) {
        if (obase + c < out_size) dout[obase + c] = g_boxes[b][t][c] * kf;
    }
    int lbpos = NUMB * PRE * 8 + b * PRE + t;
    if (lbpos < out_size) dout[lbpos] = 0.0f;
    int kppos = NUMB * PRE * 9 + b * PRE + t;
    if (kppos < out_size) dout[kppos] = kf;
}

// ---------------- launcher ----------------
extern "C" void kernel_launch(void* const* d_in, const int* in_sizes, int n_in,
                              void* d_out, int out_size) {
    const float* feat  = (const float*)d_in[0];
    const int*   bidx  = (const int*)d_in[1];
    const int*   coor  = (const int*)d_in[2];
    const float* Wc    = (const float*)d_in[3];
    const float* bc    = (const float*)d_in[4];
    const float* Wr    = (const float*)d_in[5];
    const float* br    = (const float*)d_in[6];
    float* out = (float*)d_out;

    const int N = in_sizes[1];

    k_score<<<(N + 255) / 256, 256>>>(feat, bidx, Wc, bc, Wr, br, N);
    k_thresh<<<NUMB, 1024>>>();
    k_compact<<<(N + 511) / 512, 256>>>(bidx, N);
    k_rescore<<<dim3(32, NUMB), 256>>>(feat, Wc, bc, Wr, br, N);
    k_rank_leaf<<<dim3(4, NUMB), 1024>>>();
    k_rank_m1<<<dim3(2, NUMB), 1024>>>();
    k_rank_m2f<<<NUMB, 1024>>>(coor);
    k_mask<<<dim3(PRE / 32, NUMB), 1024>>>();
    k_scan_out<<<NUMB, 1024>>>(out, out_size);
}

// round 15
// speedup vs baseline: 1.3990x; 1.1752x over previous
#include <cuda_runtime.h>
#include <cstdint>
#include <math.h>

#define NUMB   4
#define PRE    1024
#define CAND   2048
#define HBINS  65536
#define MAXN   200000
#define TOPK   1280

// ---------------- device scratch (static, no runtime alloc) ----------------
// Self-cleaning across graph replays:
//  - g_hist / g_ccnt: zeroed by k_thresh after reading (BSS-zeroed at start).
//  - g_rowflag: zeroed by k_rank_m1f before k_mask ORs into it.
//  - g_cand: stale slots ignored via g_ccnt bound in k_rescore.
__device__ unsigned long long g_keyarr[MAXN];
__device__ unsigned           g_hist[NUMB][HBINS];
__device__ unsigned           g_thr[NUMB];
__device__ int                g_ccnt[NUMB];
__device__ unsigned long long g_cand[NUMB][CAND];
__device__ unsigned long long g_prec[NUMB][CAND];
__device__ float              g_regs[NUMB][CAND][8];
__device__ unsigned long long g_sel[NUMB][PRE];
__device__ float              g_boxes[NUMB][PRE][8];
__device__ unsigned           g_mask[NUMB][PRE][32];
__device__ unsigned           g_rowflag[NUMB][32];

// fast double exp: ~3e-13 rel error, ~13 DP ops (vs libdevice ~40+ and DDIV)
__device__ __forceinline__ double fast_exp_d(double x) {
    double y = x * 1.4426950408889634;          // x / ln2
    int ni = __double2int_rn(y);
    double f = y - (double)ni;                   // [-0.5, 0.5]
    double g = f * 0.6931471805599453;           // [-0.347, 0.347]
    double p = 1.0 / 3628800.0;
    p = p * g + 1.0 / 362880.0;
    p = p * g + 1.0 / 40320.0;
    p = p * g + 1.0 / 5040.0;
    p = p * g + 1.0 / 720.0;
    p = p * g + 1.0 / 120.0;
    p = p * g + 1.0 / 24.0;
    p = p * g + 1.0 / 6.0;
    p = p * g + 0.5;
    p = p * g + 1.0;
    p = p * g + 1.0;
    long long bits = __double_as_longlong(p) + ((long long)ni << 52);
    return __longlong_as_double(bits);
}

// ---------------- K1: APPROX score pass + histogram (prefetch-pipelined) --
__global__ void __launch_bounds__(256) k_score(
        const float* __restrict__ feat,
        const int*   __restrict__ bidx,
        const float* __restrict__ Wc,
        const float* __restrict__ bc,
        const float* __restrict__ Wr,
        const float* __restrict__ br,
        int N) {
    const int warp = threadIdx.x >> 5;
    const int lane = threadIdx.x & 31;
    const int j    = lane & 15;
    const int sub  = lane >> 4;

    float wd[4][4], w8[4][4];
#pragma unroll
    for (int q = 0; q < 4; q++) {
#pragma unroll
        for (int e = 0; e < 4; e++) {
            int f = 4 * (j + 16 * q) + e;
            wd[q][e] = Wc[f * 2 + 1] - Wc[f * 2 + 0];
            w8[q][e] = Wr[f * 9 + 8];
        }
    }
    const float bd  = bc[1] - bc[0];
    const float b8r = br[8];

    const int base0 = blockIdx.x * 256 + warp * 32;

    float4 c0, c1, c2, c3;
    {
        int p = base0 + sub;
        if (p < N) {
            const float4* f4 = (const float4*)(feat + (size_t)p * 256);
            c0 = f4[j]; c1 = f4[j + 16]; c2 = f4[j + 32]; c3 = f4[j + 48];
        } else {
            c0 = c1 = c2 = c3 = make_float4(0.f, 0.f, 0.f, 0.f);
        }
    }

    for (int it = 0; it < 16; it++) {
        float4 n0, n1, n2, n3;
        int pn = base0 + (it + 1) * 2 + sub;
        if (it < 15 && pn < N) {
            const float4* f4n = (const float4*)(feat + (size_t)pn * 256);
            n0 = f4n[j]; n1 = f4n[j + 16]; n2 = f4n[j + 32]; n3 = f4n[j + 48];
        } else {
            n0 = n1 = n2 = n3 = make_float4(0.f, 0.f, 0.f, 0.f);
        }

        float d0 = c0.x * wd[0][0] + c0.y * wd[0][1] + c0.z * wd[0][2] + c0.w * wd[0][3];
        float d1 = c1.x * wd[1][0] + c1.y * wd[1][1] + c1.z * wd[1][2] + c1.w * wd[1][3];
        float d2 = c2.x * wd[2][0] + c2.y * wd[2][1] + c2.z * wd[2][2] + c2.w * wd[2][3];
        float d3 = c3.x * wd[3][0] + c3.y * wd[3][1] + c3.z * wd[3][2] + c3.w * wd[3][3];
        float accd = (d0 + d1) + (d2 + d3);
        float r0 = c0.x * w8[0][0] + c0.y * w8[0][1] + c0.z * w8[0][2] + c0.w * w8[0][3];
        float r1 = c1.x * w8[1][0] + c1.y * w8[1][1] + c1.z * w8[1][2] + c1.w * w8[1][3];
        float r2 = c2.x * w8[2][0] + c2.y * w8[2][1] + c2.z * w8[2][2] + c2.w * w8[2][3];
        float r3 = c3.x * w8[3][0] + c3.y * w8[3][1] + c3.z * w8[3][2] + c3.w * w8[3][3];
        float accr = (r0 + r1) + (r2 + r3);

#pragma unroll
        for (int o = 8; o > 0; o >>= 1) {
            accd += __shfl_xor_sync(0xffffffffu, accd, o);
            accr += __shfl_xor_sync(0xffffffffu, accr, o);
        }
        int p_cur = base0 + it * 2 + sub;
        if (j == 0 && p_cur < N) {
            float s = 1.0f / ((1.0f + expf(-(accd + bd))) * (1.0f + expf(-(accr + b8r))));
            unsigned sb = __float_as_uint(s);
            g_keyarr[p_cur] = ((unsigned long long)sb << 32) | (unsigned)(~(unsigned)p_cur);
            atomicAdd(&g_hist[bidx[p_cur]][sb >> 16], 1u);
        }
        c0 = n0; c1 = n1; c2 = n2; c3 = n3;
    }
}

// ---------------- K2: fused threshold + hist/ccnt re-zero -----------------
__global__ void __launch_bounds__(1024) k_thresh() {
    const int b = blockIdx.x;
    const int t = threadIdx.x;
    __shared__ unsigned tsum[1024];

    uint4* h4 = (uint4*)&g_hist[b][0];
    uint4 v4[16];
    unsigned mysum = 0;
#pragma unroll
    for (int i = 0; i < 16; i++) {
        v4[i] = h4[t * 16 + i];
        mysum += v4[i].x + v4[i].y + v4[i].z + v4[i].w;
    }
#pragma unroll
    for (int i = 0; i < 16; i++) h4[t * 16 + i] = make_uint4(0, 0, 0, 0);
    if (t == 0) g_ccnt[b] = 0;

    tsum[t] = mysum;
    __syncthreads();
    for (int off = 1; off < 1024; off <<= 1) {
        unsigned add = (t + off < 1024) ? tsum[t + off] : 0;
        __syncthreads();
        tsum[t] += add;
        __syncthreads();
    }
    unsigned total = tsum[0];
    unsigned S = (t < 1023) ? tsum[t + 1] : 0;
    if (t == 0 && total < TOPK) g_thr[b] = 0u;
    if (total >= TOPK && S < TOPK && S + mysum >= TOPK) {
        unsigned acc = S;
        int bin = -1;
#pragma unroll
        for (int i = 15; i >= 0; i--) {
            unsigned w0 = v4[i].x, w1 = v4[i].y, w2 = v4[i].z, w3 = v4[i].w;
            if (bin < 0) { acc += w3; if (acc >= TOPK) bin = i * 4 + 3; }
            if (bin < 0) { acc += w2; if (acc >= TOPK) bin = i * 4 + 2; }
            if (bin < 0) { acc += w1; if (acc >= TOPK) bin = i * 4 + 1; }
            if (bin < 0) { acc += w0; if (acc >= TOPK) bin = i * 4 + 0; }
        }
        g_thr[b] = ((unsigned)(t * 64 + bin)) << 16;
    }
}

// ---------------- K3: compact (2 pts/thread, warp-aggregated atomics) -----
__global__ void k_compact(const int* __restrict__ bidx, int N) {
    const int base = (blockIdx.x * 256 + threadIdx.x) * 2;
    const unsigned lane = threadIdx.x & 31;
    unsigned long long key0 = 0ull, key1 = 0ull;
    int b0 = -1, b1 = -1;
    bool p0 = false, p1 = false;
    if (base + 1 < N) {
        ulonglong2 kk = *(const ulonglong2*)&g_keyarr[base];
        int2 bb = *(const int2*)&bidx[base];
        key0 = kk.x; key1 = kk.y; b0 = bb.x; b1 = bb.y;
        p0 = ((unsigned)(key0 >> 32) >= g_thr[b0]);
        p1 = ((unsigned)(key1 >> 32) >= g_thr[b1]);
    } else if (base < N) {
        key0 = g_keyarr[base]; b0 = bidx[base];
        p0 = ((unsigned)(key0 >> 32) >= g_thr[b0]);
    }
#pragma unroll
    for (int s = 0; s < 2; s++) {
        bool pr = s ? p1 : p0;
        int bv = s ? b1 : b0;
        unsigned long long kv = s ? key1 : key0;
#pragma unroll
        for (int bb = 0; bb < NUMB; bb++) {
            unsigned m = __ballot_sync(0xffffffffu, pr && (bv == bb));
            if (m) {
                int leader = __ffs(m) - 1;
                int base2 = 0;
                if ((int)lane == leader) base2 = atomicAdd(&g_ccnt[bb], __popc(m));
                base2 = __shfl_sync(0xffffffffu, base2, leader);
                if (pr && (bv == bb)) {
                    int slot = base2 + __popc(m & ((1u << lane) - 1u));
                    if (slot < CAND) g_cand[bb][slot] = kv;
                }
            }
        }
    }
}

// ---------------- K4: PRECISE rescore + reg-head (warp-per-candidate) -----
// grid (CAND/8, NUMB) x 256 threads; cheap-fp64 score epilogue.
// Output key: score(32) | (0x3FFFF - idx)(18) | slot(12).
__global__ void __launch_bounds__(256) k_rescore(
        const float* __restrict__ feat,
        const float* __restrict__ Wc,
        const float* __restrict__ bc,
        const float* __restrict__ Wr,
        const float* __restrict__ br,
        int N) {
    __shared__ float swc0[256], swc1[256], sw8[256];
    __shared__ float sWr[256 * 8];
    for (int i = threadIdx.x; i < 256; i += 256) {
        swc0[i] = Wc[2 * i + 0];
        swc1[i] = Wc[2 * i + 1];
        sw8[i]  = Wr[9 * i + 8];
    }
    for (int i = threadIdx.x; i < 256 * 8; i += 256) {
        int f = i >> 3, o = i & 7;
        sWr[i] = Wr[f * 9 + o];
    }
    __syncthreads();

    const int b = blockIdx.y;
    const int warp = threadIdx.x >> 5;
    const int lane = threadIdx.x & 31;
    const int k = blockIdx.x * 8 + warp;

    int cnt = g_ccnt[b];
    if (cnt > CAND) cnt = CAND;

    unsigned long long key = g_cand[b][k];
    unsigned idx = ~(unsigned)(key & 0xffffffffu);
    bool valid = (k < cnt) && (idx < (unsigned)N);

    if (!valid) {
        if (lane == 0) g_prec[b][k] = 0ull;
        return;
    }

    const float4* f4 = (const float4*)(feat + (size_t)idx * 256);
    float4 a  = f4[lane * 2 + 0];
    float4 c4 = f4[lane * 2 + 1];
    float fv[8] = {a.x, a.y, a.z, a.w, c4.x, c4.y, c4.z, c4.w};

    // compensated dots for the 3 score features
    float s0 = 0.f, comp0 = 0.f, s1 = 0.f, comp1 = 0.f, s2 = 0.f, comp2 = 0.f;
#pragma unroll
    for (int c = 0; c < 8; c++) {
        float v = fv[c];
        {
            float w = swc0[lane * 8 + c];
            float p = __fmul_rn(v, w);
            float e = __fmaf_rn(v, w, -p);
            float t = __fadd_rn(s0, p);
            float bv = __fadd_rn(t, -s0);
            comp0 = __fadd_rn(comp0, __fadd_rn(__fadd_rn(s0, -__fadd_rn(t, -bv)),
                                               __fadd_rn(p, -bv)));
            comp0 = __fadd_rn(comp0, e);
            s0 = t;
        }
        {
            float w = swc1[lane * 8 + c];
            float p = __fmul_rn(v, w);
            float e = __fmaf_rn(v, w, -p);
            float t = __fadd_rn(s1, p);
            float bv = __fadd_rn(t, -s1);
            comp1 = __fadd_rn(comp1, __fadd_rn(__fadd_rn(s1, -__fadd_rn(t, -bv)),
                                               __fadd_rn(p, -bv)));
            comp1 = __fadd_rn(comp1, e);
            s1 = t;
        }
        {
            float w = sw8[lane * 8 + c];
            float p = __fmul_rn(v, w);
            float e = __fmaf_rn(v, w, -p);
            float t = __fadd_rn(s2, p);
            float bv = __fadd_rn(t, -s2);
            comp2 = __fadd_rn(comp2, __fadd_rn(__fadd_rn(s2, -__fadd_rn(t, -bv)),
                                               __fadd_rn(p, -bv)));
            comp2 = __fadd_rn(comp2, e);
            s2 = t;
        }
    }
    double dd = ((double)s1 + (double)comp1) - ((double)s0 + (double)comp0);
    double dr = (double)s2 + (double)comp2;

    // reg head: 8 outputs, plain f32
    float ra[8];
#pragma unroll
    for (int o = 0; o < 8; o++) ra[o] = 0.0f;
    const float* wr = &sWr[lane * 64];
#pragma unroll
    for (int c = 0; c < 8; c++) {
        float v = fv[c];
#pragma unroll
        for (int o = 0; o < 8; o++)
            ra[o] = __fmaf_rn(v, wr[c * 8 + o], ra[o]);
    }

#pragma unroll
    for (int o = 16; o > 0; o >>= 1) {
        dd += __shfl_xor_sync(0xffffffffu, dd, o);
        dr += __shfl_xor_sync(0xffffffffu, dr, o);
    }
#pragma unroll
    for (int j2 = 0; j2 < 8; j2++)
#pragma unroll
        for (int o = 16; o > 0; o >>= 1)
            ra[j2] += __shfl_xor_sync(0xffffffffu, ra[j2], o);

    if (lane < 8) g_regs[b][k][lane] = __fadd_rn(ra[lane], br[lane]);
    if (lane == 0) {
        double da = dd + ((double)bc[1] - (double)bc[0]);   // l1 - l0
        double r8 = dr + (double)br[8];
        double ea = fast_exp_d(-da);
        double eb = fast_exp_d(-r8);
        double w  = (1.0 + ea) * (1.0 + eb);                // score = 1/w
        double r  = (double)(1.0f / (float)w);
        r = r * (2.0 - w * r);
        r = r * (2.0 - w * r);
        float sf = (float)r;
        unsigned long long outk =
            ((unsigned long long)__float_as_uint(sf) << 32) |
            ((unsigned long long)(0x3FFFFu - idx) << 12) |
            (unsigned long long)k;
        g_prec[b][k] = outk;
    }
}

// ---------------- K5a: sort each 1024-chunk descending (2 per batch) ------
__global__ void k_rank_leaf() {
    const int b = blockIdx.y;
    const int c = blockIdx.x;
    const int t = threadIdx.x;
    __shared__ unsigned long long s[1024];
    s[t] = g_prec[b][c * 1024 + t];

    for (unsigned k = 2; k <= 1024; k <<= 1) {
        for (unsigned jj = k >> 1; jj > 0; jj >>= 1) {
            __syncthreads();
            unsigned ixj = t ^ jj;
            if (ixj > (unsigned)t) {
                unsigned long long a = s[t], bb = s[ixj];
                bool desc = ((t & k) == 0);
                if (desc ? (a < bb) : (a > bb)) { s[t] = bb; s[ixj] = a; }
            }
        }
    }
    __syncthreads();
    g_prec[b][c * 1024 + t] = s[t];
}

// ---------------- K5b: final merge + box assembly + rowflag clean ---------
__global__ void k_rank_m1f(const int* __restrict__ coor) {
    const int b = blockIdx.x;
    const int t = threadIdx.x;
    __shared__ unsigned long long s[2048];
    if (t < 32) g_rowflag[b][t] = 0;        // self-clean before k_mask
    s[t]        = g_prec[b][t];
    s[2047 - t] = g_prec[b][1024 + t];
    for (unsigned jj = 1024; jj > 0; jj >>= 1) {
        __syncthreads();
#pragma unroll
        for (int rr = 0; rr < 2; rr++) {
            unsigned tt = t + rr * 1024;
            unsigned ixj = tt ^ jj;
            if (ixj > tt) {
                unsigned long long a = s[tt], bb = s[ixj];
                if (a < bb) { s[tt] = bb; s[ixj] = a; }
            }
        }
    }
    __syncthreads();
    unsigned long long key = s[t];
    g_sel[b][t] = key;

    float out[8];
    if (key != 0ull) {
        unsigned slot = (unsigned)(key & 0xFFFu);
        unsigned idx  = 0x3FFFFu - (unsigned)((key >> 12) & 0x3FFFFu);
        float4 ra = ((const float4*)g_regs[b][slot])[0];
        float4 rb = ((const float4*)g_regs[b][slot])[1];
        float cx = __fmul_rn((float)coor[(size_t)idx * 2 + 0], 0.8f);
        float cy = __fmul_rn((float)coor[(size_t)idx * 2 + 1], 0.8f);
        out[0] = __fadd_rn(cx, ra.x);
        out[1] = __fadd_rn(cy, ra.y);
        out[2] = ra.z;
        out[3] = expf(fminf(fmaxf(ra.w, -6.0f), 6.0f));
        out[4] = expf(fminf(fmaxf(rb.x, -6.0f), 6.0f));
        out[5] = expf(fminf(fmaxf(rb.y, -6.0f), 6.0f));
        out[6] = atan2f(rb.z, rb.w);
        out[7] = __uint_as_float((unsigned)(key >> 32));
    } else {
#pragma unroll
        for (int j2 = 0; j2 < 8; j2++) out[j2] = 0.0f;
    }
#pragma unroll
    for (int j2 = 0; j2 < 8; j2++) g_boxes[b][t][j2] = out[j2];
}

// ---------------- K6: IoU suppression bitmask (parallel) ------------------
__global__ void k_mask() {
    const int b = blockIdx.y;
    const int j = threadIdx.x;
    __shared__ float sx1[PRE], sx2[PRE], sy1[PRE], sy2[PRE], sa[PRE];

    float x = g_boxes[b][j][0], y = g_boxes[b][j][1];
    float l = g_boxes[b][j][3], w = g_boxes[b][j][4];
    bool jv = (g_sel[b][j] != 0ull);
    if (jv) {
        float lh = __fmul_rn(l, 0.5f);
        float wh = __fmul_rn(w, 0.5f);
        sx1[j] = __fadd_rn(x, -lh); sx2[j] = __fadd_rn(x, lh);
        sy1[j] = __fadd_rn(y, -wh); sy2[j] = __fadd_rn(y, wh);
        sa[j]  = __fmul_rn(l, w);
    } else {
        sx1[j] = 1e30f; sx2[j] = -1e30f;
        sy1[j] = 1e30f; sy2[j] = -1e30f;
        sa[j]  = 0.0f;
    }
    __syncthreads();

    const int i0 = blockIdx.x * 32;
    const float X1 = sx1[j], X2 = sx2[j], Y1 = sy1[j], Y2 = sy2[j], A = sa[j];
    for (int ii = 0; ii < 32; ii++) {
        int i = i0 + ii;
        float ix = fmaxf(__fadd_rn(fminf(sx2[i], X2), -fmaxf(sx1[i], X1)), 0.0f);
        float iy = fmaxf(__fadd_rn(fminf(sy2[i], Y2), -fmaxf(sy1[i], Y1)), 0.0f);
        float inter = __fmul_rn(ix, iy);
        float uni = __fadd_rn(__fadd_rn(sa[i], A), -inter);
        float iou = __fdiv_rn(inter, fmaxf(uni, 1e-6f));
        bool s = (j > i) && (iou > 0.1f);
        unsigned bal = __ballot_sync(0xffffffffu, s);
        if ((j & 31) == 0) {
            g_mask[b][i][j >> 5] = bal;
            if (bal) atomicOr(&g_rowflag[b][i >> 5], 1u << (i & 31));
        }
    }
}

// ---------------- K7: serial greedy scan (sparse rows only) + outputs -----
__global__ void k_scan_out(float* __restrict__ dout, int out_size) {
    const int b = blockIdx.x;
    const int t = threadIdx.x;
    __shared__ unsigned srem[32];

    if (t < 32) {
        unsigned rem = 0;
        unsigned flags = g_rowflag[b][t];
        for (int w = 0; w < 32; w++) {
            unsigned fw = __shfl_sync(0xffffffffu, flags, w);
            while (fw) {
                int bp = __ffs(fw) - 1;
                fw &= fw - 1;
                int i = w * 32 + bp;
                unsigned owner = __shfl_sync(0xffffffffu, rem, i >> 5);
                if (!((owner >> (i & 31)) & 1u)) {
                    rem |= g_mask[b][i][t];
                }
            }
        }
        srem[t] = rem;
    }
    __syncthreads();

    bool jv = (g_sel[b][t] != 0ull);
    bool keep = jv && !((srem[t >> 5] >> (t & 31)) & 1u);
    float kf = keep ? 1.0f : 0.0f;

    int obase = (b * PRE + t) * 8;
#pragma unroll
    for (int c = 0; c < 8; c++) {
        if (obase + c < out_size) dout[obase + c] = g_boxes[b][t][c] * kf;
    }
    int lbpos = NUMB * PRE * 8 + b * PRE + t;
    if (lbpos < out_size) dout[lbpos] = 0.0f;
    int kppos = NUMB * PRE * 9 + b * PRE + t;
    if (kppos < out_size) dout[kppos] = kf;
}

// ---------------- launcher ----------------
extern "C" void kernel_launch(void* const* d_in, const int* in_sizes, int n_in,
                              void* d_out, int out_size) {
    const float* feat  = (const float*)d_in[0];
    const int*   bidx  = (const int*)d_in[1];
    const int*   coor  = (const int*)d_in[2];
    const float* Wc    = (const float*)d_in[3];
    const float* bc    = (const float*)d_in[4];
    const float* Wr    = (const float*)d_in[5];
    const float* br    = (const float*)d_in[6];
    float* out = (float*)d_out;

    const int N = in_sizes[1];

    k_score<<<(N + 255) / 256, 256>>>(feat, bidx, Wc, bc, Wr, br, N);
    k_thresh<<<NUMB, 1024>>>();
    k_compact<<<(N + 511) / 512, 256>>>(bidx, N);
    k_rescore<<<dim3(CAND / 8, NUMB), 256>>>(feat, Wc, bc, Wr, br, N);
    k_rank_leaf<<<dim3(2, NUMB), 1024>>>();
    k_rank_m1f<<<NUMB, 1024>>>(coor);
    k_mask<<<dim3(PRE / 32, NUMB), 1024>>>();
    k_scan_out<<<NUMB, 1024>>>(out, out_size);
}